// round 13
// baseline (speedup 1.0000x reference)
#include <cuda_runtime.h>
#include <math.h>

#define BB 2
#define RR 512
#define CC 512
#define EE 256
#define HH 16
#define DD 16

typedef unsigned long long u64;

// ---------------- packed f32x2 helpers (sm_103a) ----------------
__device__ __forceinline__ u64 fma2(u64 a, u64 b, u64 c) {
    u64 d; asm("fma.rn.f32x2 %0, %1, %2, %3;" : "=l"(d) : "l"(a), "l"(b), "l"(c)); return d;
}
__device__ __forceinline__ u64 mul2(u64 a, u64 b) {
    u64 d; asm("mul.rn.f32x2 %0, %1, %2;" : "=l"(d) : "l"(a), "l"(b)); return d;
}
__device__ __forceinline__ u64 pack2(float lo, float hi) {
    u64 d; asm("mov.b64 %0, {%1, %2};" : "=l"(d) : "f"(lo), "f"(hi)); return d;
}
__device__ __forceinline__ void unpack2(u64 v, float& lo, float& hi) {
    asm("mov.b64 {%0, %1}, %2;" : "=f"(lo), "=f"(hi) : "l"(v));
}

// ---------------- scratch (device globals; no allocations) ----------------
__device__ __align__(16) float g_qv[BB*RR*2*EE];          // [B*R, 512] : q | v1
__device__ __align__(16) float g_kv[BB*CC*2*EE];          // [B*C, 512] : k | v2
__device__ __align__(16) float g_ms[(size_t)BB*HH*RR*CC]; // [b,h,r,c]
__device__ __align__(16) float g_o1[BB*RR*EE];
__device__ __align__(16) float g_o2[BB*CC*EE];
__device__ __align__(16) float g_W1t[16*256];             // W1 dot part TRANSPOSED: [h][i]
__device__ __align__(16) float g_W2t[256*16];             // W2 transposed: [i][h]
__device__ __align__(16) float g_w1c[256];                // cost column sums
__device__ __align__(4) unsigned char g_mask[BB*RR*CC];   // 1 = valid
__device__ __align__(4) unsigned char g_av1[BB*RR];       // any valid in row
__device__ __align__(4) unsigned char g_av2[BB*CC];       // any valid in col
__device__ int g_maskflags;                               // 0-init, OR-only: idempotent
__device__ int g_tile_ctr;                                // reset by prep each launch

// ---------------- weight prep (+ ticket reset) ----------------
__global__ void prep_weights_kernel(const float* __restrict__ W1,
                                    const float* __restrict__ W2) {
    int idx = blockIdx.x * 256 + threadIdx.x;     // 4096
    if (idx == 0) g_tile_ctr = 0;                 // reset persistent-ms tickets
    int i = idx >> 4, h = idx & 15;
    g_W1t[h*256 + i] = W1[i*32 + 2*h];
    g_W2t[i*16 + h]  = W2[h*256 + i];
    if (h == 0) {
        float s = 0.f;
        #pragma unroll
        for (int hh = 0; hh < 16; hh++) s += W1[i*32 + 2*hh + 1];
        g_w1c[i] = s;
    }
}

// ---------------- mask dtype detection ----------------
__global__ void mask_detect_kernel(const unsigned int* __restrict__ mw) {
    int i = blockIdx.x * 256 + threadIdx.x;   // 131072 words = first 512KB
    unsigned int v = mw[i];
    bool isf = (v == 0x3F800000u);
    bool isb = (v > 1u) && !isf;
    unsigned bf = __ballot_sync(0xffffffffu, isf);
    unsigned bb = __ballot_sync(0xffffffffu, isb);
    if ((threadIdx.x & 31) == 0) {
        if (bf) atomicOr(&g_maskflags, 2);
        if (bb) atomicOr(&g_maskflags, 1);
    }
}

// ---------------- tiled GEMM body: C[M,N] = A[M,K] @ W[N,K]^T -------------
__device__ __forceinline__ void gemm_body(
    const float* __restrict__ A, const float* __restrict__ W,
    float* __restrict__ C, int N, int K, int bm, int bn) {
    __shared__ float As[64*17];
    __shared__ float Ws[64*17];
    int t = threadIdx.x;
    int ty = t >> 4, tx = t & 15;
    float acc[4][4];
    #pragma unroll
    for (int i = 0; i < 4; i++)
        #pragma unroll
        for (int j = 0; j < 4; j++) acc[i][j] = 0.f;

    int lrow = t >> 2, lcol = (t & 3) * 4;
    for (int k0 = 0; k0 < K; k0 += 16) {
        float4 va = *(const float4*)&A[(size_t)(bm + lrow)*K + k0 + lcol];
        float4 vw = *(const float4*)&W[(size_t)(bn + lrow)*K + k0 + lcol];
        As[lrow*17 + lcol+0] = va.x; As[lrow*17 + lcol+1] = va.y;
        As[lrow*17 + lcol+2] = va.z; As[lrow*17 + lcol+3] = va.w;
        Ws[lrow*17 + lcol+0] = vw.x; Ws[lrow*17 + lcol+1] = vw.y;
        Ws[lrow*17 + lcol+2] = vw.z; Ws[lrow*17 + lcol+3] = vw.w;
        __syncthreads();
        #pragma unroll
        for (int k = 0; k < 16; k++) {
            float a[4], b[4];
            #pragma unroll
            for (int i = 0; i < 4; i++) a[i] = As[(ty*4+i)*17 + k];
            #pragma unroll
            for (int j = 0; j < 4; j++) b[j] = Ws[(tx*4+j)*17 + k];
            #pragma unroll
            for (int i = 0; i < 4; i++)
                #pragma unroll
                for (int j = 0; j < 4; j++)
                    acc[i][j] = fmaf(a[i], b[j], acc[i][j]);
        }
        __syncthreads();
    }
    #pragma unroll
    for (int i = 0; i < 4; i++) {
        float4 v = make_float4(acc[i][0], acc[i][1], acc[i][2], acc[i][3]);
        *(float4*)&C[(size_t)(bm + ty*4 + i)*N + bn + tx*4] = v;
    }
}

// fused: z=0 -> qv = x1@Wqv1^T, z=1 -> kv = x2@Wkv2^T, z>=2 -> mask canon
__global__ void __launch_bounds__(256) gemm_proj_canon_kernel(
    const float* __restrict__ x1, const float* __restrict__ Wqv1,
    const float* __restrict__ x2, const float* __restrict__ Wkv2,
    const void* __restrict__ m) {
    int z = blockIdx.z;
    if (z < 2) {
        const float* A = z ? x2 : x1;
        const float* W = z ? Wkv2 : Wqv1;
        float* C = z ? g_kv : g_qv;
        gemm_body(A, W, C, 512, 256, blockIdx.y * 64, blockIdx.x * 64);
        return;
    }
    // mask canonicalization: 2048 virtual blocks over 524288 elements
    int cid = (z - 2) * 128 + blockIdx.y * 8 + blockIdx.x;
    int i = cid * 256 + threadIdx.x;
    int f = g_maskflags;
    unsigned char v;
    if (f & 2)      v = (((const float*)m)[i] != 0.0f) ? 1 : 0;
    else if (f & 1) v = ((const unsigned char*)m)[i] ? 1 : 0;
    else            v = ((const int*)m)[i] ? 1 : 0;
    g_mask[i] = v;
    unsigned vb = __ballot_sync(0xffffffffu, v != 0);
    if (vb && (threadIdx.x & 31) == 0) g_av1[i >> 9] = 1;   // row any-valid
    if (v) g_av2[((i >> 18) << 9) + (i & 511)] = 1;          // col any-valid
}

// fused output projections
__global__ void __launch_bounds__(256) gemm_out_kernel(
    const float* __restrict__ Wout1, const float* __restrict__ Wout2,
    float* __restrict__ out) {
    int z = blockIdx.z;
    const float* A = z ? g_o2 : g_o1;
    const float* W = z ? Wout2 : Wout1;
    float* C = out + (size_t)z * 1024 * 256;
    gemm_body(A, W, C, 256, 256, blockIdx.y * 64, blockIdx.x * 64);
}

// ---------------- mixed-score MLP: PERSISTENT, dynamic tickets ------------
// 296 CTAs (2/SM); weights staged once; tiles (16r x 32c) claimed via atomic.
__global__ void __launch_bounds__(256, 2) ms_kernel(const float* __restrict__ cost) {
    __shared__ float Qs[16*260];
    __shared__ float Ks[32*260];
    __shared__ u64   sW1[16*128];   // g_W1t as u64 pairs: [h][i/2]
    __shared__ u64   sW2[256*8];    // g_W2t as u64 pairs: [i][h/2]
    __shared__ float sWc[256];
    __shared__ int   s_tk;

    int t = threadIdx.x, ty = t >> 4, tx = t & 15;

    // stage weights ONCE per CTA
    for (int idx = t; idx < 1024; idx += 256) {
        ((float4*)sW1)[idx] = ((const float4*)g_W1t)[idx];
        ((float4*)sW2)[idx] = ((const float4*)g_W2t)[idx];
    }
    if (t < 64) ((float4*)sWc)[t] = ((const float4*)g_w1c)[t];

    while (true) {
        if (t == 0) s_tk = atomicAdd(&g_tile_ctr, 1);
        __syncthreads();                 // ticket visible; weights/smem safe
        int tk = s_tk;
        if (tk >= 1024) break;           // uniform across block
        int b  = tk >> 9;
        int r0 = ((tk >> 4) & 31) << 4;
        int c0 = (tk & 15) << 5;

        for (int idx = t; idx < 16*64; idx += 256) {
            int row = idx >> 6, c4 = (idx & 63) << 2;
            *(float4*)&Qs[row*260 + c4] = *(const float4*)&g_qv[((size_t)b*RR + (r0 + row))*512 + c4];
        }
        for (int idx = t; idx < 32*64; idx += 256) {
            int row = idx >> 6, c4 = (idx & 63) << 2;
            *(float4*)&Ks[row*260 + c4] = *(const float4*)&g_kv[((size_t)b*CC + (c0 + row))*512 + c4];
        }
        __syncthreads();

        u64 dd0[16], dd1[16];
        {
            const float4* qrow = reinterpret_cast<const float4*>(Qs + ty*260);
            const float4* kr0  = reinterpret_cast<const float4*>(Ks + tx*260);
            const float4* kr1  = reinterpret_cast<const float4*>(Ks + (tx+16)*260);
            #pragma unroll
            for (int h = 0; h < 16; h++) {
                float4 q0 = qrow[h*4+0], q1 = qrow[h*4+1], q2 = qrow[h*4+2], q3 = qrow[h*4+3];
                float a0, a1;
                {
                    float4 k0 = kr0[h*4+0], k1 = kr0[h*4+1], k2 = kr0[h*4+2], k3 = kr0[h*4+3];
                    float a = q0.x*k0.x;
                    a = fmaf(q0.y,k0.y,a); a = fmaf(q0.z,k0.z,a); a = fmaf(q0.w,k0.w,a);
                    a = fmaf(q1.x,k1.x,a); a = fmaf(q1.y,k1.y,a); a = fmaf(q1.z,k1.z,a); a = fmaf(q1.w,k1.w,a);
                    a = fmaf(q2.x,k2.x,a); a = fmaf(q2.y,k2.y,a); a = fmaf(q2.z,k2.z,a); a = fmaf(q2.w,k2.w,a);
                    a = fmaf(q3.x,k3.x,a); a = fmaf(q3.y,k3.y,a); a = fmaf(q3.z,k3.z,a); a = fmaf(q3.w,k3.w,a);
                    a0 = a * 0.25f;
                }
                {
                    float4 k0 = kr1[h*4+0], k1 = kr1[h*4+1], k2 = kr1[h*4+2], k3 = kr1[h*4+3];
                    float a = q0.x*k0.x;
                    a = fmaf(q0.y,k0.y,a); a = fmaf(q0.z,k0.z,a); a = fmaf(q0.w,k0.w,a);
                    a = fmaf(q1.x,k1.x,a); a = fmaf(q1.y,k1.y,a); a = fmaf(q1.z,k1.z,a); a = fmaf(q1.w,k1.w,a);
                    a = fmaf(q2.x,k2.x,a); a = fmaf(q2.y,k2.y,a); a = fmaf(q2.z,k2.z,a); a = fmaf(q2.w,k2.w,a);
                    a = fmaf(q3.x,k3.x,a); a = fmaf(q3.y,k3.y,a); a = fmaf(q3.z,k3.z,a); a = fmaf(q3.w,k3.w,a);
                    a1 = a * 0.25f;
                }
                dd0[h] = pack2(a0, a0);
                dd1[h] = pack2(a1, a1);
            }
        }

        float cva = cost[((size_t)b*RR + (r0 + ty))*CC + (c0 + tx)];
        float cvb = cost[((size_t)b*RR + (r0 + ty))*CC + (c0 + tx + 16)];
        u64 cv0 = pack2(cva, cva);
        u64 cv1 = pack2(cvb, cvb);

        u64 ms0[8], ms1[8];
        #pragma unroll
        for (int j = 0; j < 8; j++) { ms0[j] = 0ull; ms1[j] = 0ull; }

        #pragma unroll 1
        for (int i0 = 0; i0 < 256; i0 += 4) {
            int q = i0 >> 2;
            float4 wc4 = *(const float4*)&sWc[i0];
            u64 wcA = pack2(wc4.x, wc4.y), wcB = pack2(wc4.z, wc4.w);
            u64 hA0 = mul2(wcA, cv0), hB0 = mul2(wcB, cv0);
            u64 hA1 = mul2(wcA, cv1), hB1 = mul2(wcB, cv1);
            #pragma unroll
            for (int h = 0; h < 16; h++) {
                ulonglong2 w = reinterpret_cast<const ulonglong2*>(sW1 + h*128)[q];
                hA0 = fma2(w.x, dd0[h], hA0);
                hB0 = fma2(w.y, dd0[h], hB0);
                hA1 = fma2(w.x, dd1[h], hA1);
                hB1 = fma2(w.y, dd1[h], hB1);
            }
            float a0,a1,b0,b1, c0f,c1f,d0,d1;
            unpack2(hA0, a0, a1); unpack2(hB0, b0, b1);
            unpack2(hA1, c0f, c1f); unpack2(hB1, d0, d1);
            a0=fmaxf(a0,0.f); a1=fmaxf(a1,0.f); b0=fmaxf(b0,0.f); b1=fmaxf(b1,0.f);
            c0f=fmaxf(c0f,0.f); c1f=fmaxf(c1f,0.f); d0=fmaxf(d0,0.f); d1=fmaxf(d1,0.f);
            u64 hb0[4] = { pack2(a0,a0), pack2(a1,a1), pack2(b0,b0), pack2(b1,b1) };
            u64 hb1[4] = { pack2(c0f,c0f), pack2(c1f,c1f), pack2(d0,d0), pack2(d1,d1) };
            #pragma unroll
            for (int u = 0; u < 4; u++) {
                const ulonglong2* wr = reinterpret_cast<const ulonglong2*>(sW2 + (i0+u)*8);
                ulonglong2 wA = wr[0], wB = wr[1], wC = wr[2], wD = wr[3];
                ms0[0] = fma2(wA.x, hb0[u], ms0[0]); ms0[1] = fma2(wA.y, hb0[u], ms0[1]);
                ms0[2] = fma2(wB.x, hb0[u], ms0[2]); ms0[3] = fma2(wB.y, hb0[u], ms0[3]);
                ms0[4] = fma2(wC.x, hb0[u], ms0[4]); ms0[5] = fma2(wC.y, hb0[u], ms0[5]);
                ms0[6] = fma2(wD.x, hb0[u], ms0[6]); ms0[7] = fma2(wD.y, hb0[u], ms0[7]);
                ms1[0] = fma2(wA.x, hb1[u], ms1[0]); ms1[1] = fma2(wA.y, hb1[u], ms1[1]);
                ms1[2] = fma2(wB.x, hb1[u], ms1[2]); ms1[3] = fma2(wB.y, hb1[u], ms1[3]);
                ms1[4] = fma2(wC.x, hb1[u], ms1[4]); ms1[5] = fma2(wC.y, hb1[u], ms1[5]);
                ms1[6] = fma2(wD.x, hb1[u], ms1[6]); ms1[7] = fma2(wD.y, hb1[u], ms1[7]);
            }
        }

        size_t ob0 = ((size_t)b*HH*RR + (size_t)(r0 + ty))*CC + (c0 + tx);
        #pragma unroll
        for (int j = 0; j < 8; j++) {
            float lo, hi;
            unpack2(ms0[j], lo, hi);
            g_ms[ob0 + (size_t)(2*j)  *RR*CC] = lo;
            g_ms[ob0 + (size_t)(2*j+1)*RR*CC] = hi;
            unpack2(ms1[j], lo, hi);
            g_ms[ob0 + 16 + (size_t)(2*j)  *RR*CC] = lo;
            g_ms[ob0 + 16 + (size_t)(2*j+1)*RR*CC] = hi;
        }
    }
}

// ---------------- fused attention: register-resident V, 3 CTA/SM ----------
__global__ void __launch_bounds__(256, 3) attn_kernel(float* __restrict__ o1,
                                                      float* __restrict__ o2) {
    __shared__ float tw[16*520];
    __shared__ float vs[512*16];      // aliased as pacc after combine
    __shared__ float sinv[16];
    int z = blockIdx.z;
    int dir = z >> 1, b = z & 1;
    int h = blockIdx.y;
    int t = threadIdx.x;
    size_t msbase = ((size_t)(b*HH + h))*RR*CC;

    // ---- stage V tile [k][d] (dir0: v2 rows=c; dir1: v1 rows=r) ----
    const float* vbase = dir ? (g_qv + (size_t)b*RR*512 + 256 + h*16)
                             : (g_kv + (size_t)b*CC*512 + 256 + h*16);
    for (int idx = t; idx < 2048; idx += 256) {
        int k = idx >> 2, f = (idx & 3) * 4;
        *(float4*)&vs[k*16 + f] = *(const float4*)&vbase[(size_t)k*512 + f];
    }

    // ---- stage logits+mask into tw[out16][k512] ----
    if (dir == 0) {
        int r0 = blockIdx.x * 16;
        for (int idx = t; idx < 2048; idx += 256) {
            int row = idx >> 7, cq = (idx & 127) << 2;
            int r = r0 + row;
            float4 lv = *(const float4*)&g_ms[msbase + (size_t)r*CC + cq];
            uchar4 mk = *(const uchar4*)&g_mask[((size_t)b*RR + r)*CC + cq];
            bool anyv = g_av1[b*RR + r] != 0;
            float* dst = &tw[row*520 + cq];
            dst[0] = (!anyv || mk.x) ? lv.x : -INFINITY;
            dst[1] = (!anyv || mk.y) ? lv.y : -INFINITY;
            dst[2] = (!anyv || mk.z) ? lv.z : -INFINITY;
            dst[3] = (!anyv || mk.w) ? lv.w : -INFINITY;
        }
    } else {
        int c0 = blockIdx.x * 16;
        for (int idx = t; idx < 2048; idx += 256) {
            int r = idx >> 2, q = (idx & 3) << 2;   // 4 j's per float4
            float4 lv = *(const float4*)&g_ms[msbase + (size_t)r*CC + c0 + q];
            uchar4 mk = *(const uchar4*)&g_mask[((size_t)b*RR + r)*CC + c0 + q];
            uchar4 av = *(const uchar4*)&g_av2[b*CC + c0 + q];
            tw[(q+0)*520 + r] = (!av.x || mk.x) ? lv.x : -INFINITY;
            tw[(q+1)*520 + r] = (!av.y || mk.y) ? lv.y : -INFINITY;
            tw[(q+2)*520 + r] = (!av.z || mk.z) ? lv.z : -INFINITY;
            tw[(q+3)*520 + r] = (!av.w || mk.w) ? lv.w : -INFINITY;
        }
    }
    __syncthreads();

    // ---- softmax per output row (contiguous in tw) ----
    {
        int row = t >> 4, g = t & 15;
        float* tr = tw + row*520;
        float mx = -INFINITY;
        #pragma unroll 8
        for (int k = 0; k < 32; k++) mx = fmaxf(mx, tr[g + 16*k]);
        #pragma unroll
        for (int o = 8; o; o >>= 1) mx = fmaxf(mx, __shfl_xor_sync(0xffffffffu, mx, o));
        float s = 0.f;
        #pragma unroll 8
        for (int k = 0; k < 32; k++) {
            float e = __expf(tr[g + 16*k] - mx);
            tr[g + 16*k] = e; s += e;
        }
        #pragma unroll
        for (int o = 8; o; o >>= 1) s += __shfl_xor_sync(0xffffffffu, s, o);
        if (g == 0) sinv[row] = 1.f / s;
    }
    __syncthreads();

    // ---- combine: thread (d = t&15, cp = t>>4); K split in 2 segments ----
    int d = t & 15, cp = t >> 4;
    float acc[16];
    #pragma unroll
    for (int ro = 0; ro < 16; ro++) acc[ro] = 0.f;

    #pragma unroll 1
    for (int seg = 0; seg < 2; seg++) {
        float vreg[16];
        int kbase = cp*32 + seg*16;
        #pragma unroll
        for (int k = 0; k < 16; k++) vreg[k] = vs[(kbase + k)*16 + d];
        const float* twp = tw + kbase;
        #pragma unroll
        for (int ro = 0; ro < 16; ro++) {
            const float4* w4 = (const float4*)(twp + ro*520);
            float a = acc[ro];
            #pragma unroll
            for (int k4 = 0; k4 < 4; k4++) {
                float4 w = w4[k4];
                a = fmaf(w.x, vreg[k4*4+0], a);
                a = fmaf(w.y, vreg[k4*4+1], a);
                a = fmaf(w.z, vreg[k4*4+2], a);
                a = fmaf(w.w, vreg[k4*4+3], a);
            }
            acc[ro] = a;
        }
    }
    __syncthreads();   // all vs reads done; safe to alias as pacc

    // partial sums into pacc (aliases vs): [ro][d][cp] padded 17
    float* pacc = vs;
    #pragma unroll
    for (int ro = 0; ro < 16; ro++)
        pacc[ro*272 + d*17 + cp] = acc[ro];
    __syncthreads();

    // ---- final reduction over cp + scale + store ----
    {
        int ro = t >> 4, dd = t & 15;
        const float* p = &pacc[ro*272 + dd*17];
        float s = 0.f;
        #pragma unroll
        for (int c = 0; c < 16; c++) s += p[c];
        s *= sinv[ro];
        if (dir == 0) {
            int r0 = blockIdx.x * 16;
            o1[((size_t)b*RR + r0 + ro)*EE + h*16 + dd] = s;
        } else {
            int c0 = blockIdx.x * 16;
            o2[((size_t)b*CC + c0 + ro)*EE + h*16 + dd] = s;
        }
    }
}

// ---------------- launcher ----------------
extern "C" void kernel_launch(void* const* d_in, const int* in_sizes, int n_in,
                              void* d_out, int out_size) {
    const float* x1    = (const float*)d_in[0];
    const float* x2    = (const float*)d_in[1];
    const void*  maskp = d_in[2];
    const float* cost  = (const float*)d_in[3];
    const float* Wqv1  = (const float*)d_in[4];
    const float* Wkv2  = (const float*)d_in[5];
    const float* W1    = (const float*)d_in[6];
    const float* W2    = (const float*)d_in[7];
    const float* Wout1 = (const float*)d_in[8];
    const float* Wout2 = (const float*)d_in[9];
    float* out = (float*)d_out;

    void *p_o1, *p_o2;
    cudaGetSymbolAddress(&p_o1, g_o1);
    cudaGetSymbolAddress(&p_o2, g_o2);

    // #1: weight prep (+ ticket reset)   #2: mask dtype detect
    prep_weights_kernel<<<16, 256>>>(W1, W2);
    mask_detect_kernel<<<512, 256>>>((const unsigned int*)maskp);
    // #3: projections (z=0,1) + mask canonicalization (z=2..17)
    gemm_proj_canon_kernel<<<dim3(8, 16, 18), 256>>>(x1, Wqv1, x2, Wkv2, maskp);
    // #4: persistent mixed-score MLP (ncu capture slot), 2 CTAs/SM
    ms_kernel<<<296, 256>>>(cost);
    // #5: fused attention, both directions
    attn_kernel<<<dim3(32, 16, 4), 256>>>((float*)p_o1, (float*)p_o2);
    // #6: output projections into d_out: [h1 | h2]
    gemm_out_kernel<<<dim3(4, 16, 2), 256>>>(Wout1, Wout2, out);
}

// round 14
// speedup vs baseline: 1.0422x; 1.0422x over previous
#include <cuda_runtime.h>
#include <math.h>

#define BB 2
#define RR 512
#define CC 512
#define EE 256
#define HH 16
#define DD 16

typedef unsigned long long u64;

// ---------------- packed f32x2 helpers (sm_103a) ----------------
__device__ __forceinline__ u64 fma2(u64 a, u64 b, u64 c) {
    u64 d; asm("fma.rn.f32x2 %0, %1, %2, %3;" : "=l"(d) : "l"(a), "l"(b), "l"(c)); return d;
}
__device__ __forceinline__ u64 mul2(u64 a, u64 b) {
    u64 d; asm("mul.rn.f32x2 %0, %1, %2;" : "=l"(d) : "l"(a), "l"(b)); return d;
}
__device__ __forceinline__ u64 pack2(float lo, float hi) {
    u64 d; asm("mov.b64 %0, {%1, %2};" : "=l"(d) : "f"(lo), "f"(hi)); return d;
}
__device__ __forceinline__ void unpack2(u64 v, float& lo, float& hi) {
    asm("mov.b64 {%0, %1}, %2;" : "=f"(lo), "=f"(hi) : "l"(v));
}

// ---------------- scratch (device globals; no allocations) ----------------
__device__ __align__(16) float g_qv[BB*RR*2*EE];          // [B*R, 512] : q | v1
__device__ __align__(16) float g_kv[BB*CC*2*EE];          // [B*C, 512] : k | v2
__device__ __align__(16) float g_ms[(size_t)BB*HH*RR*CC]; // [b,h,r,c]
__device__ __align__(16) float g_o1[BB*RR*EE];
__device__ __align__(16) float g_o2[BB*CC*EE];
__device__ __align__(16) float g_W1t[16*256];             // W1 dot part TRANSPOSED: [h][i]
__device__ __align__(16) float g_W2t[256*16];             // W2 transposed: [i][h]
__device__ __align__(16) float g_w1c[256];                // cost column sums
__device__ __align__(4) unsigned char g_mask[BB*RR*CC];   // 1 = valid
__device__ __align__(4) unsigned char g_av1[BB*RR];       // any valid in row
__device__ __align__(4) unsigned char g_av2[BB*CC];       // any valid in col
__device__ int g_maskflags;                               // 0-init, OR-only: idempotent

// ---------------- fused: weight prep + mask dtype detection ----------------
__global__ void prep_detect_kernel(const float* __restrict__ W1,
                                   const float* __restrict__ W2,
                                   const unsigned int* __restrict__ mw) {
    int bid = blockIdx.x;
    if (bid < 16) {
        int idx = bid * 256 + threadIdx.x;     // 4096
        int i = idx >> 4, h = idx & 15;
        g_W1t[h*256 + i] = W1[i*32 + 2*h];
        g_W2t[i*16 + h]  = W2[h*256 + i];
        if (h == 0) {
            float s = 0.f;
            #pragma unroll
            for (int hh = 0; hh < 16; hh++) s += W1[i*32 + 2*hh + 1];
            g_w1c[i] = s;
        }
    } else {
        int i = (bid - 16) * 256 + threadIdx.x;   // 131072 words = first 512KB
        unsigned int v = mw[i];
        bool isf = (v == 0x3F800000u);
        bool isb = (v > 1u) && !isf;
        unsigned bf = __ballot_sync(0xffffffffu, isf);
        unsigned bb = __ballot_sync(0xffffffffu, isb);
        if ((threadIdx.x & 31) == 0) {
            if (bf) atomicOr(&g_maskflags, 2);
            if (bb) atomicOr(&g_maskflags, 1);
        }
    }
}

// ---------------- tiled GEMM body: C[M,N] = A[M,K] @ W[N,K]^T -------------
__device__ __forceinline__ void gemm_body(
    const float* __restrict__ A, const float* __restrict__ W,
    float* __restrict__ C, int N, int K, int bm, int bn) {
    __shared__ float As[64*17];
    __shared__ float Ws[64*17];
    int t = threadIdx.x;
    int ty = t >> 4, tx = t & 15;
    float acc[4][4];
    #pragma unroll
    for (int i = 0; i < 4; i++)
        #pragma unroll
        for (int j = 0; j < 4; j++) acc[i][j] = 0.f;

    int lrow = t >> 2, lcol = (t & 3) * 4;
    for (int k0 = 0; k0 < K; k0 += 16) {
        float4 va = *(const float4*)&A[(size_t)(bm + lrow)*K + k0 + lcol];
        float4 vw = *(const float4*)&W[(size_t)(bn + lrow)*K + k0 + lcol];
        As[lrow*17 + lcol+0] = va.x; As[lrow*17 + lcol+1] = va.y;
        As[lrow*17 + lcol+2] = va.z; As[lrow*17 + lcol+3] = va.w;
        Ws[lrow*17 + lcol+0] = vw.x; Ws[lrow*17 + lcol+1] = vw.y;
        Ws[lrow*17 + lcol+2] = vw.z; Ws[lrow*17 + lcol+3] = vw.w;
        __syncthreads();
        #pragma unroll
        for (int k = 0; k < 16; k++) {
            float a[4], b[4];
            #pragma unroll
            for (int i = 0; i < 4; i++) a[i] = As[(ty*4+i)*17 + k];
            #pragma unroll
            for (int j = 0; j < 4; j++) b[j] = Ws[(tx*4+j)*17 + k];
            #pragma unroll
            for (int i = 0; i < 4; i++)
                #pragma unroll
                for (int j = 0; j < 4; j++)
                    acc[i][j] = fmaf(a[i], b[j], acc[i][j]);
        }
        __syncthreads();
    }
    #pragma unroll
    for (int i = 0; i < 4; i++) {
        float4 v = make_float4(acc[i][0], acc[i][1], acc[i][2], acc[i][3]);
        *(float4*)&C[(size_t)(bm + ty*4 + i)*N + bn + tx*4] = v;
    }
}

// fused: z=0 -> qv = x1@Wqv1^T, z=1 -> kv = x2@Wkv2^T, z>=2 -> mask canon
__global__ void __launch_bounds__(256) gemm_proj_canon_kernel(
    const float* __restrict__ x1, const float* __restrict__ Wqv1,
    const float* __restrict__ x2, const float* __restrict__ Wkv2,
    const void* __restrict__ m) {
    int z = blockIdx.z;
    if (z < 2) {
        const float* A = z ? x2 : x1;
        const float* W = z ? Wkv2 : Wqv1;
        float* C = z ? g_kv : g_qv;
        gemm_body(A, W, C, 512, 256, blockIdx.y * 64, blockIdx.x * 64);
        return;
    }
    // mask canonicalization: 2048 virtual blocks over 524288 elements
    int cid = (z - 2) * 128 + blockIdx.y * 8 + blockIdx.x;
    int i = cid * 256 + threadIdx.x;
    int f = g_maskflags;
    unsigned char v;
    if (f & 2)      v = (((const float*)m)[i] != 0.0f) ? 1 : 0;
    else if (f & 1) v = ((const unsigned char*)m)[i] ? 1 : 0;
    else            v = ((const int*)m)[i] ? 1 : 0;
    g_mask[i] = v;
    unsigned vb = __ballot_sync(0xffffffffu, v != 0);
    if (vb && (threadIdx.x & 31) == 0) g_av1[i >> 9] = 1;   // row any-valid
    if (v) g_av2[((i >> 18) << 9) + (i & 511)] = 1;          // col any-valid
}

// fused output projections
__global__ void __launch_bounds__(256) gemm_out_kernel(
    const float* __restrict__ Wout1, const float* __restrict__ Wout2,
    float* __restrict__ out) {
    int z = blockIdx.z;
    const float* A = z ? g_o2 : g_o1;
    const float* W = z ? Wout2 : Wout1;
    float* C = out + (size_t)z * 1024 * 256;
    gemm_body(A, W, C, 256, 256, blockIdx.y * 64, blockIdx.x * 64);
}

// ---------------- mixed-score MLP: 2 pairs/thread (PROVEN 176us config) ---
__global__ void __launch_bounds__(256, 2) ms_kernel(const float* __restrict__ cost) {
    __shared__ float Qs[16*260];
    __shared__ float Ks[32*260];
    __shared__ u64   sW1[16*128];   // g_W1t as u64 pairs: [h][i/2]
    __shared__ u64   sW2[256*8];    // g_W2t as u64 pairs: [i][h/2]
    __shared__ float sWc[256];

    int b = blockIdx.z, r0 = blockIdx.y * 16, c0 = blockIdx.x * 32;
    int t = threadIdx.x, ty = t >> 4, tx = t & 15;

    for (int idx = t; idx < 16*64; idx += 256) {
        int row = idx >> 6, c4 = (idx & 63) << 2;
        *(float4*)&Qs[row*260 + c4] = *(const float4*)&g_qv[((size_t)b*RR + (r0 + row))*512 + c4];
    }
    for (int idx = t; idx < 32*64; idx += 256) {
        int row = idx >> 6, c4 = (idx & 63) << 2;
        *(float4*)&Ks[row*260 + c4] = *(const float4*)&g_kv[((size_t)b*CC + (c0 + row))*512 + c4];
    }
    for (int idx = t; idx < 1024; idx += 256) {
        ((float4*)sW1)[idx] = ((const float4*)g_W1t)[idx];
        ((float4*)sW2)[idx] = ((const float4*)g_W2t)[idx];
    }
    if (t < 64) ((float4*)sWc)[t] = ((const float4*)g_w1c)[t];
    __syncthreads();

    u64 dd0[16], dd1[16];
    {
        const float4* qrow = reinterpret_cast<const float4*>(Qs + ty*260);
        const float4* kr0  = reinterpret_cast<const float4*>(Ks + tx*260);
        const float4* kr1  = reinterpret_cast<const float4*>(Ks + (tx+16)*260);
        #pragma unroll
        for (int h = 0; h < 16; h++) {
            float4 q0 = qrow[h*4+0], q1 = qrow[h*4+1], q2 = qrow[h*4+2], q3 = qrow[h*4+3];
            float a0, a1;
            {
                float4 k0 = kr0[h*4+0], k1 = kr0[h*4+1], k2 = kr0[h*4+2], k3 = kr0[h*4+3];
                float a = q0.x*k0.x;
                a = fmaf(q0.y,k0.y,a); a = fmaf(q0.z,k0.z,a); a = fmaf(q0.w,k0.w,a);
                a = fmaf(q1.x,k1.x,a); a = fmaf(q1.y,k1.y,a); a = fmaf(q1.z,k1.z,a); a = fmaf(q1.w,k1.w,a);
                a = fmaf(q2.x,k2.x,a); a = fmaf(q2.y,k2.y,a); a = fmaf(q2.z,k2.z,a); a = fmaf(q2.w,k2.w,a);
                a = fmaf(q3.x,k3.x,a); a = fmaf(q3.y,k3.y,a); a = fmaf(q3.z,k3.z,a); a = fmaf(q3.w,k3.w,a);
                a0 = a * 0.25f;
            }
            {
                float4 k0 = kr1[h*4+0], k1 = kr1[h*4+1], k2 = kr1[h*4+2], k3 = kr1[h*4+3];
                float a = q0.x*k0.x;
                a = fmaf(q0.y,k0.y,a); a = fmaf(q0.z,k0.z,a); a = fmaf(q0.w,k0.w,a);
                a = fmaf(q1.x,k1.x,a); a = fmaf(q1.y,k1.y,a); a = fmaf(q1.z,k1.z,a); a = fmaf(q1.w,k1.w,a);
                a = fmaf(q2.x,k2.x,a); a = fmaf(q2.y,k2.y,a); a = fmaf(q2.z,k2.z,a); a = fmaf(q2.w,k2.w,a);
                a = fmaf(q3.x,k3.x,a); a = fmaf(q3.y,k3.y,a); a = fmaf(q3.z,k3.z,a); a = fmaf(q3.w,k3.w,a);
                a1 = a * 0.25f;
            }
            dd0[h] = pack2(a0, a0);
            dd1[h] = pack2(a1, a1);
        }
    }

    float cva = cost[((size_t)b*RR + (r0 + ty))*CC + (c0 + tx)];
    float cvb = cost[((size_t)b*RR + (r0 + ty))*CC + (c0 + tx + 16)];
    u64 cv0 = pack2(cva, cva);
    u64 cv1 = pack2(cvb, cvb);

    u64 ms0[8], ms1[8];
    #pragma unroll
    for (int j = 0; j < 8; j++) { ms0[j] = 0ull; ms1[j] = 0ull; }

    #pragma unroll 1
    for (int i0 = 0; i0 < 256; i0 += 4) {
        int q = i0 >> 2;
        float4 wc4 = *(const float4*)&sWc[i0];
        u64 wcA = pack2(wc4.x, wc4.y), wcB = pack2(wc4.z, wc4.w);
        u64 hA0 = mul2(wcA, cv0), hB0 = mul2(wcB, cv0);
        u64 hA1 = mul2(wcA, cv1), hB1 = mul2(wcB, cv1);
        #pragma unroll
        for (int h = 0; h < 16; h++) {
            ulonglong2 w = reinterpret_cast<const ulonglong2*>(sW1 + h*128)[q];
            hA0 = fma2(w.x, dd0[h], hA0);
            hB0 = fma2(w.y, dd0[h], hB0);
            hA1 = fma2(w.x, dd1[h], hA1);
            hB1 = fma2(w.y, dd1[h], hB1);
        }
        float a0,a1,b0,b1, c0f,c1f,d0,d1;
        unpack2(hA0, a0, a1); unpack2(hB0, b0, b1);
        unpack2(hA1, c0f, c1f); unpack2(hB1, d0, d1);
        a0=fmaxf(a0,0.f); a1=fmaxf(a1,0.f); b0=fmaxf(b0,0.f); b1=fmaxf(b1,0.f);
        c0f=fmaxf(c0f,0.f); c1f=fmaxf(c1f,0.f); d0=fmaxf(d0,0.f); d1=fmaxf(d1,0.f);
        u64 hb0[4] = { pack2(a0,a0), pack2(a1,a1), pack2(b0,b0), pack2(b1,b1) };
        u64 hb1[4] = { pack2(c0f,c0f), pack2(c1f,c1f), pack2(d0,d0), pack2(d1,d1) };
        #pragma unroll
        for (int u = 0; u < 4; u++) {
            const ulonglong2* wr = reinterpret_cast<const ulonglong2*>(sW2 + (i0+u)*8);
            ulonglong2 wA = wr[0], wB = wr[1], wC = wr[2], wD = wr[3];
            ms0[0] = fma2(wA.x, hb0[u], ms0[0]); ms0[1] = fma2(wA.y, hb0[u], ms0[1]);
            ms0[2] = fma2(wB.x, hb0[u], ms0[2]); ms0[3] = fma2(wB.y, hb0[u], ms0[3]);
            ms0[4] = fma2(wC.x, hb0[u], ms0[4]); ms0[5] = fma2(wC.y, hb0[u], ms0[5]);
            ms0[6] = fma2(wD.x, hb0[u], ms0[6]); ms0[7] = fma2(wD.y, hb0[u], ms0[7]);
            ms1[0] = fma2(wA.x, hb1[u], ms1[0]); ms1[1] = fma2(wA.y, hb1[u], ms1[1]);
            ms1[2] = fma2(wB.x, hb1[u], ms1[2]); ms1[3] = fma2(wB.y, hb1[u], ms1[3]);
            ms1[4] = fma2(wC.x, hb1[u], ms1[4]); ms1[5] = fma2(wC.y, hb1[u], ms1[5]);
            ms1[6] = fma2(wD.x, hb1[u], ms1[6]); ms1[7] = fma2(wD.y, hb1[u], ms1[7]);
        }
    }

    size_t ob0 = ((size_t)b*HH*RR + (size_t)(r0 + ty))*CC + (c0 + tx);
    #pragma unroll
    for (int j = 0; j < 8; j++) {
        float lo, hi;
        unpack2(ms0[j], lo, hi);
        g_ms[ob0 + (size_t)(2*j)  *RR*CC] = lo;
        g_ms[ob0 + (size_t)(2*j+1)*RR*CC] = hi;
        unpack2(ms1[j], lo, hi);
        g_ms[ob0 + 16 + (size_t)(2*j)  *RR*CC] = lo;
        g_ms[ob0 + 16 + (size_t)(2*j+1)*RR*CC] = hi;
    }
}

// ---------------- fused attention: register-resident V, 3 CTA/SM ----------
__global__ void __launch_bounds__(256, 3) attn_kernel(float* __restrict__ o1,
                                                      float* __restrict__ o2) {
    __shared__ float tw[16*520];
    __shared__ float vs[512*16];      // aliased as pacc after combine
    __shared__ float sinv[16];
    int z = blockIdx.z;
    int dir = z >> 1, b = z & 1;
    int h = blockIdx.y;
    int t = threadIdx.x;
    size_t msbase = ((size_t)(b*HH + h))*RR*CC;

    // ---- stage V tile [k][d] (dir0: v2 rows=c; dir1: v1 rows=r) ----
    const float* vbase = dir ? (g_qv + (size_t)b*RR*512 + 256 + h*16)
                             : (g_kv + (size_t)b*CC*512 + 256 + h*16);
    for (int idx = t; idx < 2048; idx += 256) {
        int k = idx >> 2, f = (idx & 3) * 4;
        *(float4*)&vs[k*16 + f] = *(const float4*)&vbase[(size_t)k*512 + f];
    }

    // ---- stage logits+mask into tw[out16][k512] ----
    if (dir == 0) {
        int r0 = blockIdx.x * 16;
        for (int idx = t; idx < 2048; idx += 256) {
            int row = idx >> 7, cq = (idx & 127) << 2;
            int r = r0 + row;
            float4 lv = *(const float4*)&g_ms[msbase + (size_t)r*CC + cq];
            uchar4 mk = *(const uchar4*)&g_mask[((size_t)b*RR + r)*CC + cq];
            bool anyv = g_av1[b*RR + r] != 0;
            float* dst = &tw[row*520 + cq];
            dst[0] = (!anyv || mk.x) ? lv.x : -INFINITY;
            dst[1] = (!anyv || mk.y) ? lv.y : -INFINITY;
            dst[2] = (!anyv || mk.z) ? lv.z : -INFINITY;
            dst[3] = (!anyv || mk.w) ? lv.w : -INFINITY;
        }
    } else {
        int c0 = blockIdx.x * 16;
        for (int idx = t; idx < 2048; idx += 256) {
            int r = idx >> 2, q = (idx & 3) << 2;   // 4 j's per float4
            float4 lv = *(const float4*)&g_ms[msbase + (size_t)r*CC + c0 + q];
            uchar4 mk = *(const uchar4*)&g_mask[((size_t)b*RR + r)*CC + c0 + q];
            uchar4 av = *(const uchar4*)&g_av2[b*CC + c0 + q];
            tw[(q+0)*520 + r] = (!av.x || mk.x) ? lv.x : -INFINITY;
            tw[(q+1)*520 + r] = (!av.y || mk.y) ? lv.y : -INFINITY;
            tw[(q+2)*520 + r] = (!av.z || mk.z) ? lv.z : -INFINITY;
            tw[(q+3)*520 + r] = (!av.w || mk.w) ? lv.w : -INFINITY;
        }
    }
    __syncthreads();

    // ---- softmax per output row (contiguous in tw) ----
    {
        int row = t >> 4, g = t & 15;
        float* tr = tw + row*520;
        float mx = -INFINITY;
        #pragma unroll 8
        for (int k = 0; k < 32; k++) mx = fmaxf(mx, tr[g + 16*k]);
        #pragma unroll
        for (int o = 8; o; o >>= 1) mx = fmaxf(mx, __shfl_xor_sync(0xffffffffu, mx, o));
        float s = 0.f;
        #pragma unroll 8
        for (int k = 0; k < 32; k++) {
            float e = __expf(tr[g + 16*k] - mx);
            tr[g + 16*k] = e; s += e;
        }
        #pragma unroll
        for (int o = 8; o; o >>= 1) s += __shfl_xor_sync(0xffffffffu, s, o);
        if (g == 0) sinv[row] = 1.f / s;
    }
    __syncthreads();

    // ---- combine: thread (d = t&15, cp = t>>4); K split in 2 segments ----
    int d = t & 15, cp = t >> 4;
    float acc[16];
    #pragma unroll
    for (int ro = 0; ro < 16; ro++) acc[ro] = 0.f;

    #pragma unroll 1
    for (int seg = 0; seg < 2; seg++) {
        float vreg[16];
        int kbase = cp*32 + seg*16;
        #pragma unroll
        for (int k = 0; k < 16; k++) vreg[k] = vs[(kbase + k)*16 + d];
        const float* twp = tw + kbase;
        #pragma unroll
        for (int ro = 0; ro < 16; ro++) {
            const float4* w4 = (const float4*)(twp + ro*520);
            float a = acc[ro];
            #pragma unroll
            for (int k4 = 0; k4 < 4; k4++) {
                float4 w = w4[k4];
                a = fmaf(w.x, vreg[k4*4+0], a);
                a = fmaf(w.y, vreg[k4*4+1], a);
                a = fmaf(w.z, vreg[k4*4+2], a);
                a = fmaf(w.w, vreg[k4*4+3], a);
            }
            acc[ro] = a;
        }
    }
    __syncthreads();   // all vs reads done; safe to alias as pacc

    // partial sums into pacc (aliases vs): [ro][d][cp] padded 17
    float* pacc = vs;
    #pragma unroll
    for (int ro = 0; ro < 16; ro++)
        pacc[ro*272 + d*17 + cp] = acc[ro];
    __syncthreads();

    // ---- final reduction over cp + scale + store ----
    {
        int ro = t >> 4, dd = t & 15;
        const float* p = &pacc[ro*272 + dd*17];
        float s = 0.f;
        #pragma unroll
        for (int c = 0; c < 16; c++) s += p[c];
        s *= sinv[ro];
        if (dir == 0) {
            int r0 = blockIdx.x * 16;
            o1[((size_t)b*RR + r0 + ro)*EE + h*16 + dd] = s;
        } else {
            int c0 = blockIdx.x * 16;
            o2[((size_t)b*CC + c0 + ro)*EE + h*16 + dd] = s;
        }
    }
}

// ---------------- launcher ----------------
extern "C" void kernel_launch(void* const* d_in, const int* in_sizes, int n_in,
                              void* d_out, int out_size) {
    const float* x1    = (const float*)d_in[0];
    const float* x2    = (const float*)d_in[1];
    const void*  maskp = d_in[2];
    const float* cost  = (const float*)d_in[3];
    const float* Wqv1  = (const float*)d_in[4];
    const float* Wkv2  = (const float*)d_in[5];
    const float* W1    = (const float*)d_in[6];
    const float* W2    = (const float*)d_in[7];
    const float* Wout1 = (const float*)d_in[8];
    const float* Wout2 = (const float*)d_in[9];
    float* out = (float*)d_out;

    void *p_o1, *p_o2;
    cudaGetSymbolAddress(&p_o1, g_o1);
    cudaGetSymbolAddress(&p_o2, g_o2);

    // #1: fused weight prep + mask dtype detect
    prep_detect_kernel<<<528, 256>>>(W1, W2, (const unsigned int*)maskp);
    // #2: projections (z=0,1) + mask canonicalization (z=2..17)
    gemm_proj_canon_kernel<<<dim3(8, 16, 18), 256>>>(x1, Wqv1, x2, Wkv2, maskp);
    // #3: mixed-score MLP (proven 176us config)
    ms_kernel<<<dim3(16, 32, 2), 256>>>(cost);
    // #4: fused attention, both directions (ncu capture slot)
    attn_kernel<<<dim3(32, 16, 4), 256>>>((float*)p_o1, (float*)p_o2);
    // #5: output projections into d_out: [h1 | h2]
    gemm_out_kernel<<<dim3(4, 16, 2), 256>>>(Wout1, Wout2, out);
}

// round 15
// speedup vs baseline: 1.0533x; 1.0106x over previous
#include <cuda_runtime.h>
#include <math.h>

#define BB 2
#define RR 512
#define CC 512
#define EE 256
#define HH 16
#define DD 16

typedef unsigned long long u64;

// ---------------- packed f32x2 helpers (sm_103a) ----------------
__device__ __forceinline__ u64 fma2(u64 a, u64 b, u64 c) {
    u64 d; asm("fma.rn.f32x2 %0, %1, %2, %3;" : "=l"(d) : "l"(a), "l"(b), "l"(c)); return d;
}
__device__ __forceinline__ u64 mul2(u64 a, u64 b) {
    u64 d; asm("mul.rn.f32x2 %0, %1, %2;" : "=l"(d) : "l"(a), "l"(b)); return d;
}
__device__ __forceinline__ u64 pack2(float lo, float hi) {
    u64 d; asm("mov.b64 %0, {%1, %2};" : "=l"(d) : "f"(lo), "f"(hi)); return d;
}
__device__ __forceinline__ void unpack2(u64 v, float& lo, float& hi) {
    asm("mov.b64 {%0, %1}, %2;" : "=f"(lo), "=f"(hi) : "l"(v));
}

// ---------------- scratch (device globals; no allocations) ----------------
__device__ __align__(16) float g_qv[BB*RR*2*EE];          // [B*R, 512] : q | v1
__device__ __align__(16) float g_kv[BB*CC*2*EE];          // [B*C, 512] : k | v2
__device__ __align__(16) float g_ms[(size_t)BB*HH*RR*CC]; // [b,h,r,c]
__device__ __align__(16) float g_o1[BB*RR*EE];
__device__ __align__(16) float g_o2[BB*CC*EE];
__device__ __align__(16) float g_W1t[16*256];             // W1 dot part TRANSPOSED: [h][i]
__device__ __align__(16) float g_W2t[256*16];             // W2 transposed: [i][h]
__device__ __align__(16) float g_w1c[256];                // cost column sums
__device__ __align__(4) unsigned char g_mask[BB*RR*CC];   // 1 = valid
__device__ __align__(4) unsigned char g_av1[BB*RR];       // any valid in row
__device__ __align__(4) unsigned char g_av2[BB*CC];       // any valid in col
__device__ int g_maskflags;                               // 0-init, OR-only: idempotent

// ---------------- fused: weight prep + mask dtype detection ----------------
__global__ void prep_detect_kernel(const float* __restrict__ W1,
                                   const float* __restrict__ W2,
                                   const unsigned int* __restrict__ mw) {
    int bid = blockIdx.x;
    if (bid < 16) {
        int idx = bid * 256 + threadIdx.x;     // 4096
        int i = idx >> 4, h = idx & 15;
        g_W1t[h*256 + i] = W1[i*32 + 2*h];
        g_W2t[i*16 + h]  = W2[h*256 + i];
        if (h == 0) {
            float s = 0.f;
            #pragma unroll
            for (int hh = 0; hh < 16; hh++) s += W1[i*32 + 2*hh + 1];
            g_w1c[i] = s;
        }
    } else {
        int i = (bid - 16) * 256 + threadIdx.x;   // 131072 words = first 512KB
        unsigned int v = mw[i];
        bool isf = (v == 0x3F800000u);
        bool isb = (v > 1u) && !isf;
        unsigned bf = __ballot_sync(0xffffffffu, isf);
        unsigned bb = __ballot_sync(0xffffffffu, isb);
        if ((threadIdx.x & 31) == 0) {
            if (bf) atomicOr(&g_maskflags, 2);
            if (bb) atomicOr(&g_maskflags, 1);
        }
    }
}

// ---------------- tiled GEMM body (f32x2): C[M,N] = A[M,K] @ W[N,K]^T -----
// Tiles staged k-major: As2[k][m], Ws2[k][n] (pad 68). Inner step uses
// broadcast LDS.128 for a, paired LDS.64 for b, 8 fma2. Accumulation order
// per output element identical to the scalar version (k ascending).
__device__ __forceinline__ void gemm_body(
    const float* __restrict__ A, const float* __restrict__ W,
    float* __restrict__ C, int N, int K, int bm, int bn) {
    __shared__ __align__(16) float As2[16*68];
    __shared__ __align__(16) float Ws2[16*68];
    int t = threadIdx.x;
    int ty = t >> 4, tx = t & 15;
    u64 acc[4][2];
    #pragma unroll
    for (int i = 0; i < 4; i++) { acc[i][0] = 0ull; acc[i][1] = 0ull; }

    int lrow = t >> 2, lcol = (t & 3) * 4;
    for (int k0 = 0; k0 < K; k0 += 16) {
        float4 va = *(const float4*)&A[(size_t)(bm + lrow)*K + k0 + lcol];
        float4 vw = *(const float4*)&W[(size_t)(bn + lrow)*K + k0 + lcol];
        As2[(lcol+0)*68 + lrow] = va.x; As2[(lcol+1)*68 + lrow] = va.y;
        As2[(lcol+2)*68 + lrow] = va.z; As2[(lcol+3)*68 + lrow] = va.w;
        Ws2[(lcol+0)*68 + lrow] = vw.x; Ws2[(lcol+1)*68 + lrow] = vw.y;
        Ws2[(lcol+2)*68 + lrow] = vw.z; Ws2[(lcol+3)*68 + lrow] = vw.w;
        __syncthreads();
        #pragma unroll
        for (int k = 0; k < 16; k++) {
            float4 av = *(const float4*)&As2[k*68 + ty*4];
            u64 b01 = *(const u64*)&Ws2[k*68 + tx*4];
            u64 b23 = *(const u64*)&Ws2[k*68 + tx*4 + 2];
            u64 a0 = pack2(av.x, av.x), a1 = pack2(av.y, av.y);
            u64 a2 = pack2(av.z, av.z), a3 = pack2(av.w, av.w);
            acc[0][0] = fma2(a0, b01, acc[0][0]); acc[0][1] = fma2(a0, b23, acc[0][1]);
            acc[1][0] = fma2(a1, b01, acc[1][0]); acc[1][1] = fma2(a1, b23, acc[1][1]);
            acc[2][0] = fma2(a2, b01, acc[2][0]); acc[2][1] = fma2(a2, b23, acc[2][1]);
            acc[3][0] = fma2(a3, b01, acc[3][0]); acc[3][1] = fma2(a3, b23, acc[3][1]);
        }
        __syncthreads();
    }
    #pragma unroll
    for (int i = 0; i < 4; i++) {
        float4 v;
        unpack2(acc[i][0], v.x, v.y);
        unpack2(acc[i][1], v.z, v.w);
        *(float4*)&C[(size_t)(bm + ty*4 + i)*N + bn + tx*4] = v;
    }
}

// fused: z=0 -> qv = x1@Wqv1^T, z=1 -> kv = x2@Wkv2^T, z>=2 -> mask canon
__global__ void __launch_bounds__(256) gemm_proj_canon_kernel(
    const float* __restrict__ x1, const float* __restrict__ Wqv1,
    const float* __restrict__ x2, const float* __restrict__ Wkv2,
    const void* __restrict__ m) {
    int z = blockIdx.z;
    if (z < 2) {
        const float* A = z ? x2 : x1;
        const float* W = z ? Wkv2 : Wqv1;
        float* C = z ? g_kv : g_qv;
        gemm_body(A, W, C, 512, 256, blockIdx.y * 64, blockIdx.x * 64);
        return;
    }
    // mask canonicalization: 2048 virtual blocks over 524288 elements
    int cid = (z - 2) * 128 + blockIdx.y * 8 + blockIdx.x;
    int i = cid * 256 + threadIdx.x;
    int f = g_maskflags;
    unsigned char v;
    if (f & 2)      v = (((const float*)m)[i] != 0.0f) ? 1 : 0;
    else if (f & 1) v = ((const unsigned char*)m)[i] ? 1 : 0;
    else            v = ((const int*)m)[i] ? 1 : 0;
    g_mask[i] = v;
    unsigned vb = __ballot_sync(0xffffffffu, v != 0);
    if (vb && (threadIdx.x & 31) == 0) g_av1[i >> 9] = 1;   // row any-valid
    if (v) g_av2[((i >> 18) << 9) + (i & 511)] = 1;          // col any-valid
}

// fused output projections
__global__ void __launch_bounds__(256) gemm_out_kernel(
    const float* __restrict__ Wout1, const float* __restrict__ Wout2,
    float* __restrict__ out) {
    int z = blockIdx.z;
    const float* A = z ? g_o2 : g_o1;
    const float* W = z ? Wout2 : Wout1;
    float* C = out + (size_t)z * 1024 * 256;
    gemm_body(A, W, C, 256, 256, blockIdx.y * 64, blockIdx.x * 64);
}

// ---------------- mixed-score MLP: 2 pairs/thread (PROVEN 176us config) ---
__global__ void __launch_bounds__(256, 2) ms_kernel(const float* __restrict__ cost) {
    __shared__ float Qs[16*260];
    __shared__ float Ks[32*260];
    __shared__ u64   sW1[16*128];   // g_W1t as u64 pairs: [h][i/2]
    __shared__ u64   sW2[256*8];    // g_W2t as u64 pairs: [i][h/2]
    __shared__ float sWc[256];

    int b = blockIdx.z, r0 = blockIdx.y * 16, c0 = blockIdx.x * 32;
    int t = threadIdx.x, ty = t >> 4, tx = t & 15;

    for (int idx = t; idx < 16*64; idx += 256) {
        int row = idx >> 6, c4 = (idx & 63) << 2;
        *(float4*)&Qs[row*260 + c4] = *(const float4*)&g_qv[((size_t)b*RR + (r0 + row))*512 + c4];
    }
    for (int idx = t; idx < 32*64; idx += 256) {
        int row = idx >> 6, c4 = (idx & 63) << 2;
        *(float4*)&Ks[row*260 + c4] = *(const float4*)&g_kv[((size_t)b*CC + (c0 + row))*512 + c4];
    }
    for (int idx = t; idx < 1024; idx += 256) {
        ((float4*)sW1)[idx] = ((const float4*)g_W1t)[idx];
        ((float4*)sW2)[idx] = ((const float4*)g_W2t)[idx];
    }
    if (t < 64) ((float4*)sWc)[t] = ((const float4*)g_w1c)[t];
    __syncthreads();

    u64 dd0[16], dd1[16];
    {
        const float4* qrow = reinterpret_cast<const float4*>(Qs + ty*260);
        const float4* kr0  = reinterpret_cast<const float4*>(Ks + tx*260);
        const float4* kr1  = reinterpret_cast<const float4*>(Ks + (tx+16)*260);
        #pragma unroll
        for (int h = 0; h < 16; h++) {
            float4 q0 = qrow[h*4+0], q1 = qrow[h*4+1], q2 = qrow[h*4+2], q3 = qrow[h*4+3];
            float a0, a1;
            {
                float4 k0 = kr0[h*4+0], k1 = kr0[h*4+1], k2 = kr0[h*4+2], k3 = kr0[h*4+3];
                float a = q0.x*k0.x;
                a = fmaf(q0.y,k0.y,a); a = fmaf(q0.z,k0.z,a); a = fmaf(q0.w,k0.w,a);
                a = fmaf(q1.x,k1.x,a); a = fmaf(q1.y,k1.y,a); a = fmaf(q1.z,k1.z,a); a = fmaf(q1.w,k1.w,a);
                a = fmaf(q2.x,k2.x,a); a = fmaf(q2.y,k2.y,a); a = fmaf(q2.z,k2.z,a); a = fmaf(q2.w,k2.w,a);
                a = fmaf(q3.x,k3.x,a); a = fmaf(q3.y,k3.y,a); a = fmaf(q3.z,k3.z,a); a = fmaf(q3.w,k3.w,a);
                a0 = a * 0.25f;
            }
            {
                float4 k0 = kr1[h*4+0], k1 = kr1[h*4+1], k2 = kr1[h*4+2], k3 = kr1[h*4+3];
                float a = q0.x*k0.x;
                a = fmaf(q0.y,k0.y,a); a = fmaf(q0.z,k0.z,a); a = fmaf(q0.w,k0.w,a);
                a = fmaf(q1.x,k1.x,a); a = fmaf(q1.y,k1.y,a); a = fmaf(q1.z,k1.z,a); a = fmaf(q1.w,k1.w,a);
                a = fmaf(q2.x,k2.x,a); a = fmaf(q2.y,k2.y,a); a = fmaf(q2.z,k2.z,a); a = fmaf(q2.w,k2.w,a);
                a = fmaf(q3.x,k3.x,a); a = fmaf(q3.y,k3.y,a); a = fmaf(q3.z,k3.z,a); a = fmaf(q3.w,k3.w,a);
                a1 = a * 0.25f;
            }
            dd0[h] = pack2(a0, a0);
            dd1[h] = pack2(a1, a1);
        }
    }

    float cva = cost[((size_t)b*RR + (r0 + ty))*CC + (c0 + tx)];
    float cvb = cost[((size_t)b*RR + (r0 + ty))*CC + (c0 + tx + 16)];
    u64 cv0 = pack2(cva, cva);
    u64 cv1 = pack2(cvb, cvb);

    u64 ms0[8], ms1[8];
    #pragma unroll
    for (int j = 0; j < 8; j++) { ms0[j] = 0ull; ms1[j] = 0ull; }

    #pragma unroll 1
    for (int i0 = 0; i0 < 256; i0 += 4) {
        int q = i0 >> 2;
        float4 wc4 = *(const float4*)&sWc[i0];
        u64 wcA = pack2(wc4.x, wc4.y), wcB = pack2(wc4.z, wc4.w);
        u64 hA0 = mul2(wcA, cv0), hB0 = mul2(wcB, cv0);
        u64 hA1 = mul2(wcA, cv1), hB1 = mul2(wcB, cv1);
        #pragma unroll
        for (int h = 0; h < 16; h++) {
            ulonglong2 w = reinterpret_cast<const ulonglong2*>(sW1 + h*128)[q];
            hA0 = fma2(w.x, dd0[h], hA0);
            hB0 = fma2(w.y, dd0[h], hB0);
            hA1 = fma2(w.x, dd1[h], hA1);
            hB1 = fma2(w.y, dd1[h], hB1);
        }
        float a0,a1,b0,b1, c0f,c1f,d0,d1;
        unpack2(hA0, a0, a1); unpack2(hB0, b0, b1);
        unpack2(hA1, c0f, c1f); unpack2(hB1, d0, d1);
        a0=fmaxf(a0,0.f); a1=fmaxf(a1,0.f); b0=fmaxf(b0,0.f); b1=fmaxf(b1,0.f);
        c0f=fmaxf(c0f,0.f); c1f=fmaxf(c1f,0.f); d0=fmaxf(d0,0.f); d1=fmaxf(d1,0.f);
        u64 hb0[4] = { pack2(a0,a0), pack2(a1,a1), pack2(b0,b0), pack2(b1,b1) };
        u64 hb1[4] = { pack2(c0f,c0f), pack2(c1f,c1f), pack2(d0,d0), pack2(d1,d1) };
        #pragma unroll
        for (int u = 0; u < 4; u++) {
            const ulonglong2* wr = reinterpret_cast<const ulonglong2*>(sW2 + (i0+u)*8);
            ulonglong2 wA = wr[0], wB = wr[1], wC = wr[2], wD = wr[3];
            ms0[0] = fma2(wA.x, hb0[u], ms0[0]); ms0[1] = fma2(wA.y, hb0[u], ms0[1]);
            ms0[2] = fma2(wB.x, hb0[u], ms0[2]); ms0[3] = fma2(wB.y, hb0[u], ms0[3]);
            ms0[4] = fma2(wC.x, hb0[u], ms0[4]); ms0[5] = fma2(wC.y, hb0[u], ms0[5]);
            ms0[6] = fma2(wD.x, hb0[u], ms0[6]); ms0[7] = fma2(wD.y, hb0[u], ms0[7]);
            ms1[0] = fma2(wA.x, hb1[u], ms1[0]); ms1[1] = fma2(wA.y, hb1[u], ms1[1]);
            ms1[2] = fma2(wB.x, hb1[u], ms1[2]); ms1[3] = fma2(wB.y, hb1[u], ms1[3]);
            ms1[4] = fma2(wC.x, hb1[u], ms1[4]); ms1[5] = fma2(wC.y, hb1[u], ms1[5]);
            ms1[6] = fma2(wD.x, hb1[u], ms1[6]); ms1[7] = fma2(wD.y, hb1[u], ms1[7]);
        }
    }

    size_t ob0 = ((size_t)b*HH*RR + (size_t)(r0 + ty))*CC + (c0 + tx);
    #pragma unroll
    for (int j = 0; j < 8; j++) {
        float lo, hi;
        unpack2(ms0[j], lo, hi);
        g_ms[ob0 + (size_t)(2*j)  *RR*CC] = lo;
        g_ms[ob0 + (size_t)(2*j+1)*RR*CC] = hi;
        unpack2(ms1[j], lo, hi);
        g_ms[ob0 + 16 + (size_t)(2*j)  *RR*CC] = lo;
        g_ms[ob0 + 16 + (size_t)(2*j+1)*RR*CC] = hi;
    }
}

// ---------------- fused attention: register-resident V, 3 CTA/SM ----------
__global__ void __launch_bounds__(256, 3) attn_kernel(float* __restrict__ o1,
                                                      float* __restrict__ o2) {
    __shared__ float tw[16*520];
    __shared__ float vs[512*16];      // aliased as pacc after combine
    __shared__ float sinv[16];
    int z = blockIdx.z;
    int dir = z >> 1, b = z & 1;
    int h = blockIdx.y;
    int t = threadIdx.x;
    size_t msbase = ((size_t)(b*HH + h))*RR*CC;

    // ---- stage V tile [k][d] (dir0: v2 rows=c; dir1: v1 rows=r) ----
    const float* vbase = dir ? (g_qv + (size_t)b*RR*512 + 256 + h*16)
                             : (g_kv + (size_t)b*CC*512 + 256 + h*16);
    for (int idx = t; idx < 2048; idx += 256) {
        int k = idx >> 2, f = (idx & 3) * 4;
        *(float4*)&vs[k*16 + f] = *(const float4*)&vbase[(size_t)k*512 + f];
    }

    // ---- stage logits+mask into tw[out16][k512] ----
    if (dir == 0) {
        int r0 = blockIdx.x * 16;
        for (int idx = t; idx < 2048; idx += 256) {
            int row = idx >> 7, cq = (idx & 127) << 2;
            int r = r0 + row;
            float4 lv = *(const float4*)&g_ms[msbase + (size_t)r*CC + cq];
            uchar4 mk = *(const uchar4*)&g_mask[((size_t)b*RR + r)*CC + cq];
            bool anyv = g_av1[b*RR + r] != 0;
            float* dst = &tw[row*520 + cq];
            dst[0] = (!anyv || mk.x) ? lv.x : -INFINITY;
            dst[1] = (!anyv || mk.y) ? lv.y : -INFINITY;
            dst[2] = (!anyv || mk.z) ? lv.z : -INFINITY;
            dst[3] = (!anyv || mk.w) ? lv.w : -INFINITY;
        }
    } else {
        int c0 = blockIdx.x * 16;
        for (int idx = t; idx < 2048; idx += 256) {
            int r = idx >> 2, q = (idx & 3) << 2;   // 4 j's per float4
            float4 lv = *(const float4*)&g_ms[msbase + (size_t)r*CC + c0 + q];
            uchar4 mk = *(const uchar4*)&g_mask[((size_t)b*RR + r)*CC + c0 + q];
            uchar4 av = *(const uchar4*)&g_av2[b*CC + c0 + q];
            tw[(q+0)*520 + r] = (!av.x || mk.x) ? lv.x : -INFINITY;
            tw[(q+1)*520 + r] = (!av.y || mk.y) ? lv.y : -INFINITY;
            tw[(q+2)*520 + r] = (!av.z || mk.z) ? lv.z : -INFINITY;
            tw[(q+3)*520 + r] = (!av.w || mk.w) ? lv.w : -INFINITY;
        }
    }
    __syncthreads();

    // ---- softmax per output row (contiguous in tw) ----
    {
        int row = t >> 4, g = t & 15;
        float* tr = tw + row*520;
        float mx = -INFINITY;
        #pragma unroll 8
        for (int k = 0; k < 32; k++) mx = fmaxf(mx, tr[g + 16*k]);
        #pragma unroll
        for (int o = 8; o; o >>= 1) mx = fmaxf(mx, __shfl_xor_sync(0xffffffffu, mx, o));
        float s = 0.f;
        #pragma unroll 8
        for (int k = 0; k < 32; k++) {
            float e = __expf(tr[g + 16*k] - mx);
            tr[g + 16*k] = e; s += e;
        }
        #pragma unroll
        for (int o = 8; o; o >>= 1) s += __shfl_xor_sync(0xffffffffu, s, o);
        if (g == 0) sinv[row] = 1.f / s;
    }
    __syncthreads();

    // ---- combine: thread (d = t&15, cp = t>>4); K split in 2 segments ----
    int d = t & 15, cp = t >> 4;
    float acc[16];
    #pragma unroll
    for (int ro = 0; ro < 16; ro++) acc[ro] = 0.f;

    #pragma unroll 1
    for (int seg = 0; seg < 2; seg++) {
        float vreg[16];
        int kbase = cp*32 + seg*16;
        #pragma unroll
        for (int k = 0; k < 16; k++) vreg[k] = vs[(kbase + k)*16 + d];
        const float* twp = tw + kbase;
        #pragma unroll
        for (int ro = 0; ro < 16; ro++) {
            const float4* w4 = (const float4*)(twp + ro*520);
            float a = acc[ro];
            #pragma unroll
            for (int k4 = 0; k4 < 4; k4++) {
                float4 w = w4[k4];
                a = fmaf(w.x, vreg[k4*4+0], a);
                a = fmaf(w.y, vreg[k4*4+1], a);
                a = fmaf(w.z, vreg[k4*4+2], a);
                a = fmaf(w.w, vreg[k4*4+3], a);
            }
            acc[ro] = a;
        }
    }
    __syncthreads();   // all vs reads done; safe to alias as pacc

    // partial sums into pacc (aliases vs): [ro][d][cp] padded 17
    float* pacc = vs;
    #pragma unroll
    for (int ro = 0; ro < 16; ro++)
        pacc[ro*272 + d*17 + cp] = acc[ro];
    __syncthreads();

    // ---- final reduction over cp + scale + store ----
    {
        int ro = t >> 4, dd = t & 15;
        const float* p = &pacc[ro*272 + dd*17];
        float s = 0.f;
        #pragma unroll
        for (int c = 0; c < 16; c++) s += p[c];
        s *= sinv[ro];
        if (dir == 0) {
            int r0 = blockIdx.x * 16;
            o1[((size_t)b*RR + r0 + ro)*EE + h*16 + dd] = s;
        } else {
            int c0 = blockIdx.x * 16;
            o2[((size_t)b*CC + c0 + ro)*EE + h*16 + dd] = s;
        }
    }
}

// ---------------- launcher ----------------
extern "C" void kernel_launch(void* const* d_in, const int* in_sizes, int n_in,
                              void* d_out, int out_size) {
    const float* x1    = (const float*)d_in[0];
    const float* x2    = (const float*)d_in[1];
    const void*  maskp = d_in[2];
    const float* cost  = (const float*)d_in[3];
    const float* Wqv1  = (const float*)d_in[4];
    const float* Wkv2  = (const float*)d_in[5];
    const float* W1    = (const float*)d_in[6];
    const float* W2    = (const float*)d_in[7];
    const float* Wout1 = (const float*)d_in[8];
    const float* Wout2 = (const float*)d_in[9];
    float* out = (float*)d_out;

    void *p_o1, *p_o2;
    cudaGetSymbolAddress(&p_o1, g_o1);
    cudaGetSymbolAddress(&p_o2, g_o2);

    // #1: fused weight prep + mask dtype detect
    prep_detect_kernel<<<528, 256>>>(W1, W2, (const unsigned int*)maskp);
    // #2: projections (z=0,1, f32x2 GEMM) + mask canonicalization (z=2..17)
    gemm_proj_canon_kernel<<<dim3(8, 16, 18), 256>>>(x1, Wqv1, x2, Wkv2, maskp);
    // #3: mixed-score MLP (proven 176us config)
    ms_kernel<<<dim3(16, 32, 2), 256>>>(cost);
    // #4: fused attention, both directions (ncu capture slot)
    attn_kernel<<<dim3(32, 16, 4), 256>>>((float*)p_o1, (float*)p_o2);
    // #5: output projections into d_out: [h1 | h2]
    gemm_out_kernel<<<dim3(4, 16, 2), 256>>>(Wout1, Wout2, out);
}